// round 10
// baseline (speedup 1.0000x reference)
#include <cuda_runtime.h>
#include <cstddef>

// Problem constants (fixed by the reference):
//   B_PAIRS=2048 pairs, each pair = 44 ligand nodes + 300 protein nodes (stride 344)
//   Only the ligand segment sums (even segments) feed the MLP.
//   MLP: 128 ->256 relu -> 128 relu -> 64 relu -> 1
#define B_PAIRS 2048
#define LIG     44
#define STRIDE  344
#define F_IN    128
#define N0      256
#define N1      128
#define N2      64
#define RTILE   8          // pairs per MLP block -> grid 256
#define ATHREADS 256       // segsum block
#define BTHREADS 512       // mlp block

typedef unsigned long long u64;

// 1 MB scratch for the per-pair feature sums.
__device__ float g_xs[B_PAIRS * F_IN];

// ---------------- packed fp32x2 helpers (sm_103a FFMA2) --------------------
#define PACK_F32X2(d, lo, hi) \
    asm("mov.b64 %0, {%1, %2};" : "=l"(d) : "f"(lo), "f"(hi))
#define UNPACK_F32X2(lo, hi, v) \
    asm("mov.b64 {%0, %1}, %2;" : "=f"(lo), "=f"(hi) : "l"(v))
#define FMA_F32X2(d, a, b, c) \
    asm("fma.rn.f32x2 %0, %1, %2, %3;" : "=l"(d) : "l"(a), "l"(b), "l"(c))
#define ADD_F32X2(d, a, b) \
    asm("add.rn.f32x2 %0, %1, %2;" : "=l"(d) : "l"(a), "l"(b))

// ============================================================================
// Kernel A: ligand segment sum. One block per pair (hot 46 MB is L2-resident).
// ============================================================================
__global__ void __launch_bounds__(ATHREADS)
seg_sum_kernel(const float* __restrict__ features)
{
    __shared__ float4 part[8][32];
    const int tid  = threadIdx.x;
    const int pair = blockIdx.x;
    const int c4   = tid & 31;
    const int g    = tid >> 5;

    const float4* src = reinterpret_cast<const float4*>(features)
                      + (size_t)pair * STRIDE * (F_IN / 4) + c4;
    float4 acc = make_float4(0.f, 0.f, 0.f, 0.f);
#pragma unroll
    for (int r = g; r < LIG; r += 8) {
        float4 v = __ldcs(src + (size_t)r * (F_IN / 4));
        acc.x += v.x; acc.y += v.y; acc.z += v.z; acc.w += v.w;
    }
    part[g][c4] = acc;
    __syncthreads();

    if (tid < 32) {
        float4 s = part[0][tid];
#pragma unroll
        for (int gg = 1; gg < 8; ++gg) {
            float4 v = part[gg][tid];
            s.x += v.x; s.y += v.y; s.z += v.z; s.w += v.w;
        }
        reinterpret_cast<float4*>(g_xs)[pair * (F_IN / 4) + tid] = s;
    }
}

// ============================================================================
// Kernel B: 4-layer MLP, RTILE=8 rows per block, grid=256, 512 threads.
// Job shape: 1 column-pair (LDG.64 packed weights) x 8 rows (dup-activation
// LDS.128 broadcasts) -> 0.375 L1-cyc / 32 MACs, now with 32 warps/block
// for latency hiding. Weights still read exactly once per block.
// ============================================================================
__global__ void __launch_bounds__(BTHREADS, 2)
mlp_kernel(const float* __restrict__ W0, const float* __restrict__ b0,
           const float* __restrict__ W1, const float* __restrict__ b1,
           const float* __restrict__ W2, const float* __restrict__ b2,
           const float* __restrict__ Wout, const float* __restrict__ bout,
           float* __restrict__ out)
{
    __shared__ __align__(16) u64  xsD[F_IN][RTILE];   //  8 KB dup activations
    __shared__ __align__(16) u64  h0D[N0][RTILE];     // 16 KB
    __shared__ __align__(16) u64  h1D[N1][RTILE];     //  8 KB
    __shared__ __align__(16) float h2T[N2][RTILE];    //  2 KB
    __shared__ __align__(16) u64  pbuf[3840];         // 30 KB partials

    const int tid = threadIdx.x;
    const int p0  = blockIdx.x * RTILE;

    // Load 8 summed rows, duplicate-pack into SMEM. (256 of 512 threads)
    if (tid < 256) {
        const int pp = tid & 7;
        const int c4 = tid >> 3;                 // 0..31
        float4 v = reinterpret_cast<const float4*>(g_xs)
                       [(size_t)(p0 + pp) * (F_IN / 4) + c4];
        u64 d0, d1, d2, d3;
        PACK_F32X2(d0, v.x, v.x); PACK_F32X2(d1, v.y, v.y);
        PACK_F32X2(d2, v.z, v.z); PACK_F32X2(d3, v.w, v.w);
        xsD[c4 * 4 + 0][pp] = d0;
        xsD[c4 * 4 + 1][pp] = d1;
        xsD[c4 * 4 + 2][pp] = d2;
        xsD[c4 * 4 + 3][pp] = d3;
    }
    __syncthreads();

    // ======== Layer 0: [8,128]@[128,256]+b relu | 128 cp x 4 kq x 32 ========
    {
        const int ct = tid & 127;                // colpair: cols 2ct, 2ct+1
        const int kq = tid >> 7;                 // 0..3, 32 k each
        u64 acc[8];
#pragma unroll
        for (int r = 0; r < 8; ++r) acc[r] = 0ull;
        const float* Wp = W0 + (size_t)(kq * 32) * N0 + 2 * ct;
#pragma unroll 8
        for (int kk = 0; kk < 32; ++kk) {
            u64 w = *reinterpret_cast<const u64*>(Wp + (size_t)kk * N0);
            const u64* ap = &xsD[kq * 32 + kk][0];
            ulonglong2 a01 = *reinterpret_cast<const ulonglong2*>(ap);
            ulonglong2 a23 = *reinterpret_cast<const ulonglong2*>(ap + 2);
            ulonglong2 a45 = *reinterpret_cast<const ulonglong2*>(ap + 4);
            ulonglong2 a67 = *reinterpret_cast<const ulonglong2*>(ap + 6);
            FMA_F32X2(acc[0], a01.x, w, acc[0]);
            FMA_F32X2(acc[1], a01.y, w, acc[1]);
            FMA_F32X2(acc[2], a23.x, w, acc[2]);
            FMA_F32X2(acc[3], a23.y, w, acc[3]);
            FMA_F32X2(acc[4], a45.x, w, acc[4]);
            FMA_F32X2(acc[5], a45.y, w, acc[5]);
            FMA_F32X2(acc[6], a67.x, w, acc[6]);
            FMA_F32X2(acc[7], a67.y, w, acc[7]);
        }
        if (kq > 0) {
            u64* dst = &pbuf[((kq - 1) * 128 + ct) * 8];
#pragma unroll
            for (int r = 0; r < 8; r += 2)
                *reinterpret_cast<ulonglong2*>(dst + r) =
                    make_ulonglong2(acc[r], acc[r + 1]);
        }
        __syncthreads();
        if (kq == 0) {
#pragma unroll
            for (int t = 0; t < 3; ++t) {
                const u64* q = &pbuf[(t * 128 + ct) * 8];
#pragma unroll
                for (int r = 0; r < 8; r += 2) {
                    ulonglong2 qq = *reinterpret_cast<const ulonglong2*>(q + r);
                    ADD_F32X2(acc[r],     acc[r],     qq.x);
                    ADD_F32X2(acc[r + 1], acc[r + 1], qq.y);
                }
            }
            u64 bb = *reinterpret_cast<const u64*>(b0 + 2 * ct);
#pragma unroll
            for (int r = 0; r < 8; ++r) {
                ADD_F32X2(acc[r], acc[r], bb);
                float v0, v1; UNPACK_F32X2(v0, v1, acc[r]);
                v0 = fmaxf(v0, 0.f); v1 = fmaxf(v1, 0.f);
                u64 d0, d1; PACK_F32X2(d0, v0, v0); PACK_F32X2(d1, v1, v1);
                h0D[2 * ct    ][r] = d0;
                h0D[2 * ct + 1][r] = d1;
            }
        }
    }
    __syncthreads();

    // ======== Layer 1: [8,256]@[256,128]+b relu | 64 cp x 8 kq x 32 =========
    {
        const int ct = tid & 63;                 // colpair
        const int kq = tid >> 6;                 // 0..7, 32 k each
        u64 acc[8];
#pragma unroll
        for (int r = 0; r < 8; ++r) acc[r] = 0ull;
        const float* Wp = W1 + (size_t)(kq * 32) * N1 + 2 * ct;
#pragma unroll 8
        for (int kk = 0; kk < 32; ++kk) {
            u64 w = *reinterpret_cast<const u64*>(Wp + (size_t)kk * N1);
            const u64* ap = &h0D[kq * 32 + kk][0];
            ulonglong2 a01 = *reinterpret_cast<const ulonglong2*>(ap);
            ulonglong2 a23 = *reinterpret_cast<const ulonglong2*>(ap + 2);
            ulonglong2 a45 = *reinterpret_cast<const ulonglong2*>(ap + 4);
            ulonglong2 a67 = *reinterpret_cast<const ulonglong2*>(ap + 6);
            FMA_F32X2(acc[0], a01.x, w, acc[0]);
            FMA_F32X2(acc[1], a01.y, w, acc[1]);
            FMA_F32X2(acc[2], a23.x, w, acc[2]);
            FMA_F32X2(acc[3], a23.y, w, acc[3]);
            FMA_F32X2(acc[4], a45.x, w, acc[4]);
            FMA_F32X2(acc[5], a45.y, w, acc[5]);
            FMA_F32X2(acc[6], a67.x, w, acc[6]);
            FMA_F32X2(acc[7], a67.y, w, acc[7]);
        }
        if (kq > 0) {
            u64* dst = &pbuf[((kq - 1) * 64 + ct) * 8];
#pragma unroll
            for (int r = 0; r < 8; r += 2)
                *reinterpret_cast<ulonglong2*>(dst + r) =
                    make_ulonglong2(acc[r], acc[r + 1]);
        }
        __syncthreads();
        if (kq == 0) {
#pragma unroll
            for (int t = 0; t < 7; ++t) {
                const u64* q = &pbuf[(t * 64 + ct) * 8];
#pragma unroll
                for (int r = 0; r < 8; r += 2) {
                    ulonglong2 qq = *reinterpret_cast<const ulonglong2*>(q + r);
                    ADD_F32X2(acc[r],     acc[r],     qq.x);
                    ADD_F32X2(acc[r + 1], acc[r + 1], qq.y);
                }
            }
            u64 bb = *reinterpret_cast<const u64*>(b1 + 2 * ct);
#pragma unroll
            for (int r = 0; r < 8; ++r) {
                ADD_F32X2(acc[r], acc[r], bb);
                float v0, v1; UNPACK_F32X2(v0, v1, acc[r]);
                v0 = fmaxf(v0, 0.f); v1 = fmaxf(v1, 0.f);
                u64 d0, d1; PACK_F32X2(d0, v0, v0); PACK_F32X2(d1, v1, v1);
                h1D[2 * ct    ][r] = d0;
                h1D[2 * ct + 1][r] = d1;
            }
        }
    }
    __syncthreads();

    // ======== Layer 2: [8,128]@[128,64]+b relu | 32 cp x 16 kq x 8 ==========
    {
        const int ct = tid & 31;                 // colpair
        const int kq = tid >> 5;                 // 0..15, 8 k each
        u64 acc[8];
#pragma unroll
        for (int r = 0; r < 8; ++r) acc[r] = 0ull;
        const float* Wp = W2 + (size_t)(kq * 8) * N2 + 2 * ct;
#pragma unroll
        for (int kk = 0; kk < 8; ++kk) {
            u64 w = *reinterpret_cast<const u64*>(Wp + (size_t)kk * N2);
            const u64* ap = &h1D[kq * 8 + kk][0];
            ulonglong2 a01 = *reinterpret_cast<const ulonglong2*>(ap);
            ulonglong2 a23 = *reinterpret_cast<const ulonglong2*>(ap + 2);
            ulonglong2 a45 = *reinterpret_cast<const ulonglong2*>(ap + 4);
            ulonglong2 a67 = *reinterpret_cast<const ulonglong2*>(ap + 6);
            FMA_F32X2(acc[0], a01.x, w, acc[0]);
            FMA_F32X2(acc[1], a01.y, w, acc[1]);
            FMA_F32X2(acc[2], a23.x, w, acc[2]);
            FMA_F32X2(acc[3], a23.y, w, acc[3]);
            FMA_F32X2(acc[4], a45.x, w, acc[4]);
            FMA_F32X2(acc[5], a45.y, w, acc[5]);
            FMA_F32X2(acc[6], a67.x, w, acc[6]);
            FMA_F32X2(acc[7], a67.y, w, acc[7]);
        }
        if (kq > 0) {
            u64* dst = &pbuf[((kq - 1) * 32 + ct) * 8];
#pragma unroll
            for (int r = 0; r < 8; r += 2)
                *reinterpret_cast<ulonglong2*>(dst + r) =
                    make_ulonglong2(acc[r], acc[r + 1]);
        }
        __syncthreads();
        if (kq == 0) {
#pragma unroll
            for (int t = 0; t < 15; ++t) {
                const u64* q = &pbuf[(t * 32 + ct) * 8];
#pragma unroll
                for (int r = 0; r < 8; r += 2) {
                    ulonglong2 qq = *reinterpret_cast<const ulonglong2*>(q + r);
                    ADD_F32X2(acc[r],     acc[r],     qq.x);
                    ADD_F32X2(acc[r + 1], acc[r + 1], qq.y);
                }
            }
            u64 bb = *reinterpret_cast<const u64*>(b2 + 2 * ct);
#pragma unroll
            for (int r = 0; r < 8; ++r) {
                ADD_F32X2(acc[r], acc[r], bb);
                float v0, v1; UNPACK_F32X2(v0, v1, acc[r]);
                h2T[2 * ct    ][r] = fmaxf(v0, 0.f);
                h2T[2 * ct + 1][r] = fmaxf(v1, 0.f);
            }
        }
    }
    __syncthreads();

    // ======== Output: [8,64]@[64,1]+b  (first 8 warps = 8 rows) =============
    {
        const int warp = tid >> 5;
        const int lane = tid & 31;
        if (warp < RTILE) {
            float s = h2T[2 * lane][warp]     * Wout[2 * lane]
                    + h2T[2 * lane + 1][warp] * Wout[2 * lane + 1];
#pragma unroll
            for (int o = 16; o > 0; o >>= 1)
                s += __shfl_down_sync(0xffffffffu, s, o);
            if (lane == 0)
                out[p0 + warp] = s + bout[0];
        }
    }
}

// d_in order (metadata): [0] batch_num_nodes (unused), [1] features,
// [2] W0, [3] b0, [4] W1, [5] b1, [6] W2, [7] b2, [8] Wout, [9] bout.
extern "C" void kernel_launch(void* const* d_in, const int* in_sizes, int n_in,
                              void* d_out, int out_size)
{
    const float* features = (const float*)d_in[1];
    const float* W0   = (const float*)d_in[2];
    const float* b0   = (const float*)d_in[3];
    const float* W1   = (const float*)d_in[4];
    const float* b1   = (const float*)d_in[5];
    const float* W2   = (const float*)d_in[6];
    const float* b2   = (const float*)d_in[7];
    const float* Wout = (const float*)d_in[8];
    const float* bout = (const float*)d_in[9];
    float* out = (float*)d_out;

    seg_sum_kernel<<<B_PAIRS, ATHREADS>>>(features);
    mlp_kernel<<<B_PAIRS / RTILE, BTHREADS>>>(W0, b0, W1, b1, W2, b2,
                                              Wout, bout, out);
}

// round 11
// speedup vs baseline: 1.3887x; 1.3887x over previous
#include <cuda_runtime.h>
#include <cstddef>

// Problem constants (fixed by the reference):
//   B_PAIRS=2048 pairs, each pair = 44 ligand nodes + 300 protein nodes (stride 344)
//   Only the ligand segment sums (even segments) feed the MLP.
//   MLP: 128 ->256 relu -> 128 relu -> 64 relu -> 1
#define B_PAIRS 2048
#define LIG     44
#define STRIDE  344
#define F_IN    128
#define N0      256
#define N1      128
#define N2      64
#define RTILE   8          // pairs per MLP block -> grid 256
#define THREADS 256

typedef unsigned long long u64;

// 1 MB scratch for the per-pair feature sums.
__device__ float g_xs[B_PAIRS * F_IN];

// ---------------- packed fp32x2 helpers (sm_103a FFMA2) --------------------
#define PACK_F32X2(d, lo, hi) \
    asm("mov.b64 %0, {%1, %2};" : "=l"(d) : "f"(lo), "f"(hi))
#define UNPACK_F32X2(lo, hi, v) \
    asm("mov.b64 {%0, %1}, %2;" : "=f"(lo), "=f"(hi) : "l"(v))
#define FMA_F32X2(d, a, b, c) \
    asm("fma.rn.f32x2 %0, %1, %2, %3;" : "=l"(d) : "l"(a), "l"(b), "l"(c))
#define ADD_F32X2(d, a, b) \
    asm("add.rn.f32x2 %0, %1, %2;" : "=l"(d) : "l"(a), "l"(b))

// ============================================================================
// Kernel A: ligand segment sum. One block per pair (hot 46 MB L2-resident).
// ============================================================================
__global__ void __launch_bounds__(THREADS)
seg_sum_kernel(const float* __restrict__ features)
{
    __shared__ float4 part[8][32];
    const int tid  = threadIdx.x;
    const int pair = blockIdx.x;
    const int c4   = tid & 31;
    const int g    = tid >> 5;

    const float4* src = reinterpret_cast<const float4*>(features)
                      + (size_t)pair * STRIDE * (F_IN / 4) + c4;
    float4 acc = make_float4(0.f, 0.f, 0.f, 0.f);
#pragma unroll
    for (int r = g; r < LIG; r += 8) {
        float4 v = __ldcs(src + (size_t)r * (F_IN / 4));
        acc.x += v.x; acc.y += v.y; acc.z += v.z; acc.w += v.w;
    }
    part[g][c4] = acc;
    __syncthreads();

    if (tid < 32) {
        float4 s = part[0][tid];
#pragma unroll
        for (int gg = 1; gg < 8; ++gg) {
            float4 v = part[gg][tid];
            s.x += v.x; s.y += v.y; s.z += v.z; s.w += v.w;
        }
        reinterpret_cast<float4*>(g_xs)[pair * (F_IN / 4) + tid] = s;
    }
}

// ============================================================================
// Kernel B: 4-layer MLP, RTILE=8 rows, grid=256, 256 threads.
// Activations stored RAW as row-pairs (u64 = rows (2rp, 2rp+1)); weights
// duplicated on the fly (2 ALU movs). Inner iter: 1 LDG.64 + 2 LDS.128
// broadcast + 8 FFMA2 = 4 L1-cyc per 16 lane-MACs (33% less than dup-a).
// acc[c*4+rp] = packed rows (2rp,2rp+1) of column 2ct+c.
// ============================================================================
__global__ void __launch_bounds__(THREADS)
mlp_kernel(const float* __restrict__ W0, const float* __restrict__ b0,
           const float* __restrict__ W1, const float* __restrict__ b1,
           const float* __restrict__ W2, const float* __restrict__ b2,
           const float* __restrict__ Wout, const float* __restrict__ bout,
           float* __restrict__ out)
{
    __shared__ __align__(16) u64  xsP[F_IN][RTILE / 2];  // 4 KB raw row-pairs
    __shared__ __align__(16) u64  h0P[N0][RTILE / 2];    // 8 KB
    __shared__ __align__(16) u64  h1P[N1][RTILE / 2];    // 4 KB
    __shared__ __align__(16) float h2T[N2][RTILE];       // 2 KB
    __shared__ __align__(16) u64  pbuf[7 * 32 * 8];      // 14 KB partials

    const int tid = threadIdx.x;
    const int p0  = blockIdx.x * RTILE;

    // Load 8 summed rows. Raw layout: xsP[k][rp] viewed as float[k][8].
    {
        const int pp = tid & 7;
        const int c4 = tid >> 3;                 // 0..31
        float4 v = reinterpret_cast<const float4*>(g_xs)
                       [(size_t)(p0 + pp) * (F_IN / 4) + c4];
        float* xf = reinterpret_cast<float*>(&xsP[0][0]);
        xf[(c4 * 4 + 0) * RTILE + pp] = v.x;
        xf[(c4 * 4 + 1) * RTILE + pp] = v.y;
        xf[(c4 * 4 + 2) * RTILE + pp] = v.z;
        xf[(c4 * 4 + 3) * RTILE + pp] = v.w;
    }
    __syncthreads();

    // ======== Layer 0: [8,128]@[128,256]+b relu | 128 cp x 2 kq x 64 ========
    {
        const int ct = tid & 127;                // colpair: cols 2ct, 2ct+1
        const int kq = tid >> 7;                 // 0/1, 64 k each
        u64 acc[8];
#pragma unroll
        for (int i = 0; i < 8; ++i) acc[i] = 0ull;
        const float* Wp = W0 + (size_t)(kq * 64) * N0 + 2 * ct;
#pragma unroll 8
        for (int kk = 0; kk < 64; ++kk) {
            float2 wv = *reinterpret_cast<const float2*>(Wp + (size_t)kk * N0);
            u64 wd0, wd1;
            PACK_F32X2(wd0, wv.x, wv.x);
            PACK_F32X2(wd1, wv.y, wv.y);
            const u64* ap = &xsP[kq * 64 + kk][0];
            ulonglong2 a01 = *reinterpret_cast<const ulonglong2*>(ap);
            ulonglong2 a23 = *reinterpret_cast<const ulonglong2*>(ap + 2);
            FMA_F32X2(acc[0], a01.x, wd0, acc[0]);
            FMA_F32X2(acc[1], a01.y, wd0, acc[1]);
            FMA_F32X2(acc[2], a23.x, wd0, acc[2]);
            FMA_F32X2(acc[3], a23.y, wd0, acc[3]);
            FMA_F32X2(acc[4], a01.x, wd1, acc[4]);
            FMA_F32X2(acc[5], a01.y, wd1, acc[5]);
            FMA_F32X2(acc[6], a23.x, wd1, acc[6]);
            FMA_F32X2(acc[7], a23.y, wd1, acc[7]);
        }
        if (kq == 1) {
            u64* dst = &pbuf[ct * 8];
#pragma unroll
            for (int i = 0; i < 8; i += 2)
                *reinterpret_cast<ulonglong2*>(dst + i) =
                    make_ulonglong2(acc[i], acc[i + 1]);
        }
        __syncthreads();
        if (kq == 0) {
            const u64* q = &pbuf[ct * 8];
#pragma unroll
            for (int i = 0; i < 8; i += 2) {
                ulonglong2 qq = *reinterpret_cast<const ulonglong2*>(q + i);
                ADD_F32X2(acc[i],     acc[i],     qq.x);
                ADD_F32X2(acc[i + 1], acc[i + 1], qq.y);
            }
            float2 bv = *reinterpret_cast<const float2*>(b0 + 2 * ct);
            u64 bb0, bb1;
            PACK_F32X2(bb0, bv.x, bv.x);
            PACK_F32X2(bb1, bv.y, bv.y);
#pragma unroll
            for (int i = 0; i < 8; ++i) {
                ADD_F32X2(acc[i], acc[i], (i < 4) ? bb0 : bb1);
                float v0, v1; UNPACK_F32X2(v0, v1, acc[i]);
                PACK_F32X2(acc[i], fmaxf(v0, 0.f), fmaxf(v1, 0.f));
            }
            *reinterpret_cast<ulonglong2*>(&h0P[2 * ct][0]) =
                make_ulonglong2(acc[0], acc[1]);
            *reinterpret_cast<ulonglong2*>(&h0P[2 * ct][2]) =
                make_ulonglong2(acc[2], acc[3]);
            *reinterpret_cast<ulonglong2*>(&h0P[2 * ct + 1][0]) =
                make_ulonglong2(acc[4], acc[5]);
            *reinterpret_cast<ulonglong2*>(&h0P[2 * ct + 1][2]) =
                make_ulonglong2(acc[6], acc[7]);
        }
    }
    __syncthreads();

    // ======== Layer 1: [8,256]@[256,128]+b relu | 64 cp x 4 kq x 64 =========
    {
        const int ct = tid & 63;
        const int kq = tid >> 6;                 // 0..3, 64 k each
        u64 acc[8];
#pragma unroll
        for (int i = 0; i < 8; ++i) acc[i] = 0ull;
        const float* Wp = W1 + (size_t)(kq * 64) * N1 + 2 * ct;
#pragma unroll 8
        for (int kk = 0; kk < 64; ++kk) {
            float2 wv = *reinterpret_cast<const float2*>(Wp + (size_t)kk * N1);
            u64 wd0, wd1;
            PACK_F32X2(wd0, wv.x, wv.x);
            PACK_F32X2(wd1, wv.y, wv.y);
            const u64* ap = &h0P[kq * 64 + kk][0];
            ulonglong2 a01 = *reinterpret_cast<const ulonglong2*>(ap);
            ulonglong2 a23 = *reinterpret_cast<const ulonglong2*>(ap + 2);
            FMA_F32X2(acc[0], a01.x, wd0, acc[0]);
            FMA_F32X2(acc[1], a01.y, wd0, acc[1]);
            FMA_F32X2(acc[2], a23.x, wd0, acc[2]);
            FMA_F32X2(acc[3], a23.y, wd0, acc[3]);
            FMA_F32X2(acc[4], a01.x, wd1, acc[4]);
            FMA_F32X2(acc[5], a01.y, wd1, acc[5]);
            FMA_F32X2(acc[6], a23.x, wd1, acc[6]);
            FMA_F32X2(acc[7], a23.y, wd1, acc[7]);
        }
        if (kq > 0) {
            u64* dst = &pbuf[((kq - 1) * 64 + ct) * 8];
#pragma unroll
            for (int i = 0; i < 8; i += 2)
                *reinterpret_cast<ulonglong2*>(dst + i) =
                    make_ulonglong2(acc[i], acc[i + 1]);
        }
        __syncthreads();
        if (kq == 0) {
#pragma unroll
            for (int t = 0; t < 3; ++t) {
                const u64* q = &pbuf[(t * 64 + ct) * 8];
#pragma unroll
                for (int i = 0; i < 8; i += 2) {
                    ulonglong2 qq = *reinterpret_cast<const ulonglong2*>(q + i);
                    ADD_F32X2(acc[i],     acc[i],     qq.x);
                    ADD_F32X2(acc[i + 1], acc[i + 1], qq.y);
                }
            }
            float2 bv = *reinterpret_cast<const float2*>(b1 + 2 * ct);
            u64 bb0, bb1;
            PACK_F32X2(bb0, bv.x, bv.x);
            PACK_F32X2(bb1, bv.y, bv.y);
#pragma unroll
            for (int i = 0; i < 8; ++i) {
                ADD_F32X2(acc[i], acc[i], (i < 4) ? bb0 : bb1);
                float v0, v1; UNPACK_F32X2(v0, v1, acc[i]);
                PACK_F32X2(acc[i], fmaxf(v0, 0.f), fmaxf(v1, 0.f));
            }
            *reinterpret_cast<ulonglong2*>(&h1P[2 * ct][0]) =
                make_ulonglong2(acc[0], acc[1]);
            *reinterpret_cast<ulonglong2*>(&h1P[2 * ct][2]) =
                make_ulonglong2(acc[2], acc[3]);
            *reinterpret_cast<ulonglong2*>(&h1P[2 * ct + 1][0]) =
                make_ulonglong2(acc[4], acc[5]);
            *reinterpret_cast<ulonglong2*>(&h1P[2 * ct + 1][2]) =
                make_ulonglong2(acc[6], acc[7]);
        }
    }
    __syncthreads();

    // ======== Layer 2: [8,128]@[128,64]+b relu | 32 cp x 8 kq x 16 ==========
    {
        const int ct = tid & 31;
        const int kq = tid >> 5;                 // 0..7, 16 k each
        u64 acc[8];
#pragma unroll
        for (int i = 0; i < 8; ++i) acc[i] = 0ull;
        const float* Wp = W2 + (size_t)(kq * 16) * N2 + 2 * ct;
#pragma unroll
        for (int kk = 0; kk < 16; ++kk) {
            float2 wv = *reinterpret_cast<const float2*>(Wp + (size_t)kk * N2);
            u64 wd0, wd1;
            PACK_F32X2(wd0, wv.x, wv.x);
            PACK_F32X2(wd1, wv.y, wv.y);
            const u64* ap = &h1P[kq * 16 + kk][0];
            ulonglong2 a01 = *reinterpret_cast<const ulonglong2*>(ap);
            ulonglong2 a23 = *reinterpret_cast<const ulonglong2*>(ap + 2);
            FMA_F32X2(acc[0], a01.x, wd0, acc[0]);
            FMA_F32X2(acc[1], a01.y, wd0, acc[1]);
            FMA_F32X2(acc[2], a23.x, wd0, acc[2]);
            FMA_F32X2(acc[3], a23.y, wd0, acc[3]);
            FMA_F32X2(acc[4], a01.x, wd1, acc[4]);
            FMA_F32X2(acc[5], a01.y, wd1, acc[5]);
            FMA_F32X2(acc[6], a23.x, wd1, acc[6]);
            FMA_F32X2(acc[7], a23.y, wd1, acc[7]);
        }
        if (kq > 0) {
            u64* dst = &pbuf[((kq - 1) * 32 + ct) * 8];
#pragma unroll
            for (int i = 0; i < 8; i += 2)
                *reinterpret_cast<ulonglong2*>(dst + i) =
                    make_ulonglong2(acc[i], acc[i + 1]);
        }
        __syncthreads();
        if (kq == 0) {
#pragma unroll
            for (int t = 0; t < 7; ++t) {
                const u64* q = &pbuf[(t * 32 + ct) * 8];
#pragma unroll
                for (int i = 0; i < 8; i += 2) {
                    ulonglong2 qq = *reinterpret_cast<const ulonglong2*>(q + i);
                    ADD_F32X2(acc[i],     acc[i],     qq.x);
                    ADD_F32X2(acc[i + 1], acc[i + 1], qq.y);
                }
            }
            float2 bv = *reinterpret_cast<const float2*>(b2 + 2 * ct);
            u64 bb0, bb1;
            PACK_F32X2(bb0, bv.x, bv.x);
            PACK_F32X2(bb1, bv.y, bv.y);
#pragma unroll
            for (int i = 0; i < 8; ++i) {
                ADD_F32X2(acc[i], acc[i], (i < 4) ? bb0 : bb1);
                float v0, v1; UNPACK_F32X2(v0, v1, acc[i]);
                const int c  = 2 * ct + (i >> 2);
                const int rp = i & 3;
                h2T[c][2 * rp    ] = fmaxf(v0, 0.f);
                h2T[c][2 * rp + 1] = fmaxf(v1, 0.f);
            }
        }
    }
    __syncthreads();

    // ======== Output: [8,64]@[64,1]+b  (8 warps = 8 rows) ===================
    {
        const int warp = tid >> 5;
        const int lane = tid & 31;
        float s = h2T[2 * lane][warp]     * Wout[2 * lane]
                + h2T[2 * lane + 1][warp] * Wout[2 * lane + 1];
#pragma unroll
        for (int o = 16; o > 0; o >>= 1)
            s += __shfl_down_sync(0xffffffffu, s, o);
        if (lane == 0)
            out[p0 + warp] = s + bout[0];
    }
}

// d_in order (metadata): [0] batch_num_nodes (unused), [1] features,
// [2] W0, [3] b0, [4] W1, [5] b1, [6] W2, [7] b2, [8] Wout, [9] bout.
extern "C" void kernel_launch(void* const* d_in, const int* in_sizes, int n_in,
                              void* d_out, int out_size)
{
    const float* features = (const float*)d_in[1];
    const float* W0   = (const float*)d_in[2];
    const float* b0   = (const float*)d_in[3];
    const float* W1   = (const float*)d_in[4];
    const float* b1   = (const float*)d_in[5];
    const float* W2   = (const float*)d_in[6];
    const float* b2   = (const float*)d_in[7];
    const float* Wout = (const float*)d_in[8];
    const float* bout = (const float*)d_in[9];
    float* out = (float*)d_out;

    seg_sum_kernel<<<B_PAIRS, THREADS>>>(features);
    mlp_kernel<<<B_PAIRS / RTILE, THREADS>>>(W0, b0, W1, b1, W2, b2,
                                             Wout, bout, out);
}